// round 2
// baseline (speedup 1.0000x reference)
#include <cuda_runtime.h>
#include <cuda_bf16.h>

// Problem constants (from reference: B=8192, F=256, T=32, D=6 -> N=63, L=64, P=8)
constexpr int B_      = 8192;
constexpr int F_      = 256;
constexpr int T_      = 32;
constexpr int NNODES  = 63;
constexpr int LEAVES  = 64;
constexpr int P_      = 8;

constexpr int BM = 128;   // batch rows per block
constexpr int BN = 64;    // node columns (63 real + 1 pad)
constexpr int KC = 32;    // K chunk
constexpr int NTHREADS = 256;

// Per-tree partial outputs: [T][B*P] floats = 8 MB scratch (deterministic reduction,
// avoids float atomics).
__device__ float g_partial[(size_t)T_ * B_ * P_];

__global__ __launch_bounds__(NTHREADS)
void softgbm_main_kernel(const float* __restrict__ x,
                         const float* __restrict__ W,
                         const float* __restrict__ bias,
                         const float* __restrict__ phi) {
    // smem pool: GEMM tiles (As 32x129 + Bs 32x65 = 6208 floats) unioned with
    // s_tile (128x65 = 8320 floats). Plus phi (512) and bias (64).
    __shared__ float pool[BM * (LEAVES + 1)];           // 8320 floats = 33.3 KB
    __shared__ float phi_s[LEAVES * P_];                // 512 floats
    __shared__ float b_s[BN];                           // 64 floats

    float (*As)[BM + 1] = reinterpret_cast<float (*)[BM + 1]>(pool);
    float (*Bs)[BN + 1] = reinterpret_cast<float (*)[BN + 1]>(pool + KC * (BM + 1));
    float (*s_tile)[LEAVES + 1] = reinterpret_cast<float (*)[LEAVES + 1]>(pool);

    const int tid  = threadIdx.x;
    const int t    = blockIdx.y;           // tree index
    const int row0 = blockIdx.x * BM;      // batch row base

    // Load this tree's phi [64,8] and bias [63] into smem (synced by first GEMM barrier).
    for (int i = tid; i < LEAVES * P_; i += NTHREADS)
        phi_s[i] = phi[(size_t)t * LEAVES * P_ + i];
    if (tid < BN)
        b_s[tid] = (tid < NNODES) ? bias[(size_t)t * NNODES + tid] : 0.0f;

    // ---- GEMM: acc[8][4] per thread; rows = ty*8..+7, cols = tx*4..+3 ----
    const int ty = tid >> 4;   // 0..15
    const int tx = tid & 15;   // 0..15

    float acc[8][4];
#pragma unroll
    for (int i = 0; i < 8; i++)
#pragma unroll
        for (int j = 0; j < 4; j++) acc[i][j] = 0.0f;

    const float* xg = x + (size_t)row0 * F_;
    const float* wg = W + (size_t)t * NNODES * F_;

    for (int kc = 0; kc < F_; kc += KC) {
        // Load As (transposed): 128 rows x 32 k. 1024 float4s / 256 threads = 4 each.
        // Global: coalesced along k. Smem stores: bank (k + row) % 32, conflict-free
        // because kq*4 spans {0..28 step 4} x row span {0..3} covers all 32 banks.
#pragma unroll
        for (int it = 0; it < 4; it++) {
            int f  = it * NTHREADS + tid;   // 0..1023
            int r  = f >> 3;                // row 0..127
            int kq = f & 7;                 // float4 index 0..7
            float4 v = *reinterpret_cast<const float4*>(xg + (size_t)r * F_ + kc + kq * 4);
            As[kq * 4 + 0][r] = v.x;
            As[kq * 4 + 1][r] = v.y;
            As[kq * 4 + 2][r] = v.z;
            As[kq * 4 + 3][r] = v.w;
        }
        // Load Bs (transposed): 64 nodes x 32 k (node 63 zero-padded).
#pragma unroll
        for (int it = 0; it < 2; it++) {
            int f  = it * NTHREADS + tid;   // 0..511
            int n  = f >> 3;                // node 0..63
            int kq = f & 7;
            float4 v;
            if (n < NNODES)
                v = *reinterpret_cast<const float4*>(wg + (size_t)n * F_ + kc + kq * 4);
            else
                v = make_float4(0.f, 0.f, 0.f, 0.f);
            Bs[kq * 4 + 0][n] = v.x;
            Bs[kq * 4 + 1][n] = v.y;
            Bs[kq * 4 + 2][n] = v.z;
            Bs[kq * 4 + 3][n] = v.w;
        }
        __syncthreads();

#pragma unroll
        for (int k = 0; k < KC; k++) {
            float a[8], bb[4];
#pragma unroll
            for (int i = 0; i < 8; i++) a[i] = As[k][ty * 8 + i];
#pragma unroll
            for (int j = 0; j < 4; j++) bb[j] = Bs[k][tx * 4 + j];
#pragma unroll
            for (int i = 0; i < 8; i++)
#pragma unroll
                for (int j = 0; j < 4; j++)
                    acc[i][j] = fmaf(a[i], bb[j], acc[i][j]);
        }
        __syncthreads();
    }

    // ---- Epilogue: bias + sigmoid into s_tile (stride 65 kills bank conflicts) ----
#pragma unroll
    for (int i = 0; i < 8; i++) {
        int r = ty * 8 + i;
#pragma unroll
        for (int j = 0; j < 4; j++) {
            int c = tx * 4 + j;
            float v = acc[i][j] + b_s[c];
            s_tile[r][c] = 1.0f / (1.0f + __expf(-v));
        }
    }
    __syncthreads();

    // ---- Leaf probabilities + phi contraction ----
    // 2 threads per row; each handles 32 of the 64 leaves.
    const int r = tid >> 1;     // 0..127
    const int q = tid & 1;      // leaf half

    float partial[P_];
#pragma unroll
    for (int p = 0; p < P_; p++) partial[p] = 0.0f;

#pragma unroll
    for (int li = 0; li < 32; li++) {
        int l = q * 32 + li;
        float pr = 1.0f;
#pragma unroll
        for (int d = 0; d < 6; d++) {
            int node = (1 << d) - 1 + (l >> (6 - d));
            int bit  = (l >> (5 - d)) & 1;
            float sv = s_tile[r][node];
            pr *= bit ? sv : (1.0f - sv);
        }
#pragma unroll
        for (int p = 0; p < P_; p++)
            partial[p] = fmaf(pr, phi_s[l * P_ + p], partial[p]);
    }

    // Reduce the two leaf-halves (adjacent lanes).
#pragma unroll
    for (int p = 0; p < P_; p++)
        partial[p] += __shfl_xor_sync(0xffffffffu, partial[p], 1);

    if (q == 0) {
        float* o = g_partial + (size_t)t * B_ * P_ + (size_t)(row0 + r) * P_;
        float4 v0 = make_float4(partial[0], partial[1], partial[2], partial[3]);
        float4 v1 = make_float4(partial[4], partial[5], partial[6], partial[7]);
        *reinterpret_cast<float4*>(o)     = v0;
        *reinterpret_cast<float4*>(o + 4) = v1;
    }
}

// Sum per-tree partials over T, apply shrinkage. out[i], i in [0, B*P).
__global__ void softgbm_reduce_kernel(float* __restrict__ out) {
    int i = blockIdx.x * blockDim.x + threadIdx.x;
    if (i >= B_ * P_) return;
    float s = 0.0f;
#pragma unroll
    for (int t = 0; t < T_; t++)
        s += g_partial[(size_t)t * B_ * P_ + i];
    out[i] = 0.1f * s;
}

extern "C" void kernel_launch(void* const* d_in, const int* in_sizes, int n_in,
                              void* d_out, int out_size) {
    (void)in_sizes; (void)n_in; (void)out_size;
    const float* x    = (const float*)d_in[0];
    const float* W    = (const float*)d_in[1];
    const float* bias = (const float*)d_in[2];
    const float* phi  = (const float*)d_in[3];
    float* out = (float*)d_out;

    dim3 grid(B_ / BM, T_);   // (64, 32) = 2048 blocks
    softgbm_main_kernel<<<grid, NTHREADS>>>(x, W, bias, phi);

    int n = B_ * P_;
    softgbm_reduce_kernel<<<(n + 255) / 256, 256>>>(out);
}

// round 4
// speedup vs baseline: 3.0150x; 3.0150x over previous
#include <cuda_runtime.h>
#include <cuda_fp16.h>
#include <cstdint>

// Problem constants: B=8192, F=256, T=32, D=6 -> N=63, L=64, P=8
constexpr int B_     = 8192;
constexpr int F_     = 256;
constexpr int T_     = 32;
constexpr int NNODES = 63;
constexpr int LEAVES = 64;
constexpr int P_     = 8;

constexpr int BM = 128;
constexpr int BN = 64;
constexpr int NTHREADS = 256;   // 8 warps: warp grid 4(m) x 2(n), warp tile 32x32

constexpr int LDA = F_ + 8;     // 264 halfs per row (16B pad -> conflict-free frag loads)
constexpr int LDB = F_ + 8;
constexpr int SMEM_A_BYTES = BM * LDA * 2;               // 67584
constexpr int SMEM_B_BYTES = BN * LDB * 2;               // 33792
constexpr int SMEM_DYN     = SMEM_A_BYTES + SMEM_B_BYTES; // 101376

// Scratch (no allocs allowed): per-tree partials + fp16-converted inputs.
__device__ __align__(16) float  g_partial[(size_t)T_ * B_ * P_];
__device__ __align__(16) __half g_xh[(size_t)B_ * F_];
__device__ __align__(16) __half g_wh[(size_t)T_ * NNODES * F_];

// ---------------- prep: fp32 -> fp16 conversion of x and W ----------------
__global__ void softgbm_prep(const float* __restrict__ x, const float* __restrict__ W) {
    int i = blockIdx.x * blockDim.x + threadIdx.x;
    constexpr int NX4 = B_ * F_ / 4;
    constexpr int NW4 = T_ * NNODES * F_ / 4;
    if (i < NX4) {
        float4 v = reinterpret_cast<const float4*>(x)[i];
        __half2* o = reinterpret_cast<__half2*>(g_xh);
        o[2 * i]     = __floats2half2_rn(v.x, v.y);
        o[2 * i + 1] = __floats2half2_rn(v.z, v.w);
    } else if (i < NX4 + NW4) {
        int j = i - NX4;
        float4 v = reinterpret_cast<const float4*>(W)[j];
        __half2* o = reinterpret_cast<__half2*>(g_wh);
        o[2 * j]     = __floats2half2_rn(v.x, v.y);
        o[2 * j + 1] = __floats2half2_rn(v.z, v.w);
    }
}

__device__ __forceinline__ void mma16816(float& c0, float& c1, float& c2, float& c3,
                                         uint32_t a0, uint32_t a1, uint32_t a2, uint32_t a3,
                                         uint32_t b0, uint32_t b1) {
    asm volatile(
        "mma.sync.aligned.m16n8k16.row.col.f32.f16.f16.f32 "
        "{%0,%1,%2,%3}, {%4,%5,%6,%7}, {%8,%9}, {%0,%1,%2,%3};"
        : "+f"(c0), "+f"(c1), "+f"(c2), "+f"(c3)
        : "r"(a0), "r"(a1), "r"(a2), "r"(a3), "r"(b0), "r"(b1));
}

// ---------------- main: HMMA GEMM + fused sigmoid/tree/phi ----------------
__global__ __launch_bounds__(NTHREADS)
void softgbm_main_kernel(const float* __restrict__ bias,
                         const float* __restrict__ phi) {
    extern __shared__ __align__(16) char dsm[];
    __shared__ float phi_s[LEAVES * P_];
    __shared__ float b_s[BN];

    __half* As = reinterpret_cast<__half*>(dsm);                      // [128][LDA]
    __half* Bs = reinterpret_cast<__half*>(dsm + SMEM_A_BYTES);       // [64][LDB]
    float (*s_tile)[LEAVES + 1] = reinterpret_cast<float (*)[LEAVES + 1]>(dsm); // union

    const int tid  = threadIdx.x;
    const int wid  = tid >> 5;
    const int lane = tid & 31;
    const int t    = blockIdx.y;
    const int row0 = blockIdx.x * BM;

    const int warp_m = wid >> 1;      // 0..3 -> rows warp_m*32
    const int warp_n = wid & 1;       // 0..1 -> cols warp_n*32
    const int gi  = lane >> 2;        // 0..7
    const int tig = lane & 3;         // 0..3

    // phi [64,8] and bias into static smem
    for (int i = tid; i < LEAVES * P_; i += NTHREADS)
        phi_s[i] = phi[(size_t)t * LEAVES * P_ + i];
    if (tid < BN)
        b_s[tid] = (tid < NNODES) ? bias[(size_t)t * NNODES + tid] : 0.0f;

    // ---- fill smem tiles (fp16, row-major, padded ld) ----
    {
        const __half* xh = g_xh + (size_t)row0 * F_;
#pragma unroll
        for (int it = 0; it < 16; it++) {               // 4096 16B chunks
            int f = it * NTHREADS + tid;
            int r = f >> 5;                              // 32 chunks/row
            int c = f & 31;
            uint4 v = *reinterpret_cast<const uint4*>(xh + (size_t)r * F_ + c * 8);
            *reinterpret_cast<uint4*>(As + (size_t)r * LDA + c * 8) = v;
        }
        const __half* wh = g_wh + (size_t)t * NNODES * F_;
#pragma unroll
        for (int it = 0; it < 8; it++) {                // 2048 16B chunks
            int f = it * NTHREADS + tid;
            int n = f >> 5;
            int c = f & 31;
            uint4 v = make_uint4(0u, 0u, 0u, 0u);
            if (n < NNODES)
                v = *reinterpret_cast<const uint4*>(wh + (size_t)n * F_ + c * 8);
            *reinterpret_cast<uint4*>(Bs + (size_t)n * LDB + c * 8) = v;
        }
    }
    __syncthreads();

    // ---- warp-tiled HMMA: 2 m16-frags x 4 n8-frags x 16 k16-steps ----
    float acc[2][4][4];
#pragma unroll
    for (int mi = 0; mi < 2; mi++)
#pragma unroll
        for (int ni = 0; ni < 4; ni++)
#pragma unroll
            for (int j = 0; j < 4; j++) acc[mi][ni][j] = 0.0f;

    const __half* a_lane = As + (size_t)(warp_m * 32 + gi) * LDA + tig * 2;
    const __half* b_lane = Bs + (size_t)(warp_n * 32 + gi) * LDB + tig * 2;

#pragma unroll
    for (int ks = 0; ks < 16; ks++) {
        const int k0 = ks * 16;
        uint32_t af[2][4];
#pragma unroll
        for (int mi = 0; mi < 2; mi++) {
            const __half* p = a_lane + (size_t)(mi * 16) * LDA + k0;
            af[mi][0] = *reinterpret_cast<const uint32_t*>(p);               // (r,   k)
            af[mi][1] = *reinterpret_cast<const uint32_t*>(p + 8 * LDA);     // (r+8, k)
            af[mi][2] = *reinterpret_cast<const uint32_t*>(p + 8);           // (r,   k+8)
            af[mi][3] = *reinterpret_cast<const uint32_t*>(p + 8 * LDA + 8); // (r+8, k+8)
        }
        uint32_t bf[4][2];
#pragma unroll
        for (int ni = 0; ni < 4; ni++) {
            const __half* p = b_lane + (size_t)(ni * 8) * LDB + k0;
            bf[ni][0] = *reinterpret_cast<const uint32_t*>(p);       // (k,   n)
            bf[ni][1] = *reinterpret_cast<const uint32_t*>(p + 8);   // (k+8, n)
        }
#pragma unroll
        for (int mi = 0; mi < 2; mi++)
#pragma unroll
            for (int ni = 0; ni < 4; ni++)
                mma16816(acc[mi][ni][0], acc[mi][ni][1], acc[mi][ni][2], acc[mi][ni][3],
                         af[mi][0], af[mi][1], af[mi][2], af[mi][3],
                         bf[ni][0], bf[ni][1]);
    }
    __syncthreads();   // done reading As/Bs; s_tile may overwrite

    // ---- bias + sigmoid in-register, scatter to s_tile ----
    // c0,c1 -> (row gi,    col tig*2, tig*2+1); c2,c3 -> (row gi+8, same cols)
#pragma unroll
    for (int mi = 0; mi < 2; mi++) {
        int r = warp_m * 32 + mi * 16 + gi;
#pragma unroll
        for (int ni = 0; ni < 4; ni++) {
            int c = warp_n * 32 + ni * 8 + tig * 2;
            float v0 = acc[mi][ni][0] + b_s[c];
            float v1 = acc[mi][ni][1] + b_s[c + 1];
            float v2 = acc[mi][ni][2] + b_s[c];
            float v3 = acc[mi][ni][3] + b_s[c + 1];
            s_tile[r][c]         = __fdividef(1.0f, 1.0f + __expf(-v0));
            s_tile[r][c + 1]     = __fdividef(1.0f, 1.0f + __expf(-v1));
            s_tile[r + 8][c]     = __fdividef(1.0f, 1.0f + __expf(-v2));
            s_tile[r + 8][c + 1] = __fdividef(1.0f, 1.0f + __expf(-v3));
        }
    }
    __syncthreads();

    // ---- leaf probabilities + phi contraction (2 threads/row, 32 leaves each) ----
    const int r = tid >> 1;
    const int q = tid & 1;

    float partial[P_];
#pragma unroll
    for (int p = 0; p < P_; p++) partial[p] = 0.0f;

#pragma unroll
    for (int li = 0; li < 32; li++) {
        int l = q * 32 + li;
        float pr = 1.0f;
#pragma unroll
        for (int d = 0; d < 6; d++) {
            int node = (1 << d) - 1 + (l >> (6 - d));
            int bit  = (l >> (5 - d)) & 1;
            float sv = s_tile[r][node];
            pr *= bit ? sv : (1.0f - sv);
        }
#pragma unroll
        for (int p = 0; p < P_; p++)
            partial[p] = fmaf(pr, phi_s[l * P_ + p], partial[p]);
    }
#pragma unroll
    for (int p = 0; p < P_; p++)
        partial[p] += __shfl_xor_sync(0xffffffffu, partial[p], 1);

    if (q == 0) {
        float* o = g_partial + (size_t)t * B_ * P_ + (size_t)(row0 + r) * P_;
        *reinterpret_cast<float4*>(o)     = make_float4(partial[0], partial[1], partial[2], partial[3]);
        *reinterpret_cast<float4*>(o + 4) = make_float4(partial[4], partial[5], partial[6], partial[7]);
    }
}

// ---------------- reduce over trees, apply shrinkage ----------------
__global__ void softgbm_reduce_kernel(float* __restrict__ out) {
    int i = blockIdx.x * blockDim.x + threadIdx.x;   // 0..B*P/4-1
    const float4* gp = reinterpret_cast<const float4*>(g_partial);
    float4 s = make_float4(0.f, 0.f, 0.f, 0.f);
#pragma unroll
    for (int t = 0; t < T_; t++) {
        float4 v = gp[(size_t)t * (B_ * P_ / 4) + i];
        s.x += v.x; s.y += v.y; s.z += v.z; s.w += v.w;
    }
    s.x *= 0.1f; s.y *= 0.1f; s.z *= 0.1f; s.w *= 0.1f;
    reinterpret_cast<float4*>(out)[i] = s;
}

extern "C" void kernel_launch(void* const* d_in, const int* in_sizes, int n_in,
                              void* d_out, int out_size) {
    (void)in_sizes; (void)n_in; (void)out_size;
    const float* x    = (const float*)d_in[0];
    const float* W    = (const float*)d_in[1];
    const float* bias = (const float*)d_in[2];
    const float* phi  = (const float*)d_in[3];
    float* out = (float*)d_out;

    cudaFuncSetAttribute(softgbm_main_kernel,
                         cudaFuncAttributeMaxDynamicSharedMemorySize, SMEM_DYN);

    constexpr int NCVT = (B_ * F_ + T_ * NNODES * F_) / 4;
    softgbm_prep<<<(NCVT + 255) / 256, 256>>>(x, W);

    dim3 grid(B_ / BM, T_);   // (64, 32)
    softgbm_main_kernel<<<grid, NTHREADS, SMEM_DYN>>>(bias, phi);

    softgbm_reduce_kernel<<<(B_ * P_ / 4) / 256, 256>>>(out);
}

// round 5
// speedup vs baseline: 3.1121x; 1.0322x over previous
#include <cuda_runtime.h>
#include <cuda_fp16.h>
#include <cstdint>

// Problem constants: B=8192, F=256, T=32, D=6 -> N=63, L=64, P=8
constexpr int B_     = 8192;
constexpr int F_     = 256;
constexpr int T_     = 32;
constexpr int NNODES = 63;
constexpr int LEAVES = 64;
constexpr int P_     = 8;

constexpr int BM = 128;
constexpr int BN = 64;
constexpr int NTHREADS = 256;        // 8 warps: 4(m) x 2(n), warp tile 32x32
constexpr int TREES_PER_BLK = 4;
constexpr int NGRP = T_ / TREES_PER_BLK;   // 8

constexpr int LDA = F_ + 8;          // 264 halfs/row -> 528B stride, 16B aligned
constexpr int LDB = F_ + 8;
constexpr int SMEM_A_BYTES = BM * LDA * 2;                 // 67584
constexpr int SMEM_B_BYTES = BN * LDB * 2;                 // 33792 (>= s_tile 33280)
constexpr int SMEM_DYN     = SMEM_A_BYTES + SMEM_B_BYTES;  // 101376 -> 2 CTAs/SM

// Per tree-group partials (deterministic reduction): 8 * 8192 * 8 floats = 2 MB.
__device__ __align__(16) float g_partial[(size_t)NGRP * B_ * P_];

__device__ __forceinline__ uint32_t smem_u32(const void* p) {
    uint32_t a;
    asm("{ .reg .u64 t; cvta.to.shared.u64 t, %1; cvt.u32.u64 %0, t; }"
        : "=r"(a) : "l"(p));
    return a;
}
__device__ __forceinline__ void ldmatrix_x4(uint32_t& r0, uint32_t& r1,
                                            uint32_t& r2, uint32_t& r3, uint32_t addr) {
    asm volatile("ldmatrix.sync.aligned.m8n8.x4.shared.b16 {%0,%1,%2,%3}, [%4];"
                 : "=r"(r0), "=r"(r1), "=r"(r2), "=r"(r3) : "r"(addr));
}
__device__ __forceinline__ void mma16816(float* c, uint32_t a0, uint32_t a1,
                                         uint32_t a2, uint32_t a3,
                                         uint32_t b0, uint32_t b1) {
    asm volatile(
        "mma.sync.aligned.m16n8k16.row.col.f32.f16.f16.f32 "
        "{%0,%1,%2,%3}, {%4,%5,%6,%7}, {%8,%9}, {%0,%1,%2,%3};"
        : "+f"(c[0]), "+f"(c[1]), "+f"(c[2]), "+f"(c[3])
        : "r"(a0), "r"(a1), "r"(a2), "r"(a3), "r"(b0), "r"(b1));
}
__device__ __forceinline__ float sigmoidf(float v) {
    return __fdividef(1.0f, 1.0f + __expf(-v));
}

__global__ __launch_bounds__(NTHREADS, 2)
void softgbm_main_kernel(const float* __restrict__ x,
                         const float* __restrict__ W,
                         const float* __restrict__ bias,
                         const float* __restrict__ phi) {
    extern __shared__ __align__(16) char dsm[];
    __shared__ float phi_s[LEAVES * P_];
    __shared__ float b_s[BN];

    __half* As = reinterpret_cast<__half*>(dsm);                 // [128][LDA]
    __half* Bs = reinterpret_cast<__half*>(dsm + SMEM_A_BYTES);  // [64][LDB]
    float (*s_tile)[LEAVES + 1] =
        reinterpret_cast<float (*)[LEAVES + 1]>(dsm + SMEM_A_BYTES);  // aliases Bs

    const int tid  = threadIdx.x;
    const int wid  = tid >> 5;
    const int lane = tid & 31;
    const int tgrp = blockIdx.y;
    const int row0 = blockIdx.x * BM;

    const int warp_m = wid >> 1;   // 0..3
    const int warp_n = wid & 1;    // 0..1
    const int gi  = lane >> 2;
    const int tig = lane & 3;

    // ---- fill As once: inline fp32 -> fp16 conversion of this block's x rows ----
#pragma unroll
    for (int it = 0; it < 16; it++) {
        int f = it * NTHREADS + tid;       // 0..4095
        int r = f >> 5;                    // row 0..127
        int c = f & 31;                    // 8-half chunk
        const float* src = x + (size_t)(row0 + r) * F_ + c * 8;
        float4 v0 = *reinterpret_cast<const float4*>(src);
        float4 v1 = *reinterpret_cast<const float4*>(src + 4);
        __half2 h[4];
        h[0] = __floats2half2_rn(v0.x, v0.y);
        h[1] = __floats2half2_rn(v0.z, v0.w);
        h[2] = __floats2half2_rn(v1.x, v1.y);
        h[3] = __floats2half2_rn(v1.z, v1.w);
        *reinterpret_cast<uint4*>(As + (size_t)r * LDA + c * 8) =
            *reinterpret_cast<uint4*>(h);
    }

    // ldmatrix lane addresses (byte smem addrs)
    const uint32_t as_u32 = smem_u32(As);
    const uint32_t bs_u32 = smem_u32(Bs);
    const uint32_t a_lm = as_u32 +
        ((uint32_t)(warp_m * 32 + (lane & 15)) * LDA + (lane >> 4) * 8) * 2;
    const uint32_t b_lm = bs_u32 +
        ((uint32_t)(warp_n * 32 + ((lane >> 4) & 1) * 8 + (lane & 7)) * LDB +
         ((lane >> 3) & 1) * 8) * 2;

    const int r_leaf = tid >> 1;   // row for leaf phase
    const int q      = tid & 1;    // subtree half

    float partial[P_];
#pragma unroll
    for (int p = 0; p < P_; p++) partial[p] = 0.0f;

    for (int it_t = 0; it_t < TREES_PER_BLK; it_t++) {
        const int t = tgrp * TREES_PER_BLK + it_t;

        // ---- fill Bs (inline convert W_t), phi, bias ----
        const float* wt = W + (size_t)t * NNODES * F_;
#pragma unroll
        for (int it = 0; it < 8; it++) {
            int f = it * NTHREADS + tid;   // 0..2047
            int n = f >> 5;
            int c = f & 31;
            __half2 h[4];
            if (n < NNODES) {
                const float* src = wt + (size_t)n * F_ + c * 8;
                float4 v0 = *reinterpret_cast<const float4*>(src);
                float4 v1 = *reinterpret_cast<const float4*>(src + 4);
                h[0] = __floats2half2_rn(v0.x, v0.y);
                h[1] = __floats2half2_rn(v0.z, v0.w);
                h[2] = __floats2half2_rn(v1.x, v1.y);
                h[3] = __floats2half2_rn(v1.z, v1.w);
            } else {
                h[0] = h[1] = h[2] = h[3] = __half2half2(__float2half(0.0f));
            }
            *reinterpret_cast<uint4*>(Bs + (size_t)n * LDB + c * 8) =
                *reinterpret_cast<uint4*>(h);
        }
        phi_s[tid]       = phi[(size_t)t * LEAVES * P_ + tid];
        phi_s[tid + 256] = phi[(size_t)t * LEAVES * P_ + tid + 256];
        if (tid < BN)
            b_s[tid] = (tid < NNODES) ? bias[(size_t)t * NNODES + tid] : 0.0f;
        __syncthreads();

        // ---- GEMM: 16 k-steps, ldmatrix fragments ----
        float acc[2][4][4];
#pragma unroll
        for (int mi = 0; mi < 2; mi++)
#pragma unroll
            for (int ni = 0; ni < 4; ni++)
#pragma unroll
                for (int j = 0; j < 4; j++) acc[mi][ni][j] = 0.0f;

#pragma unroll
        for (int ks = 0; ks < 16; ks++) {
            const uint32_t kb = (uint32_t)ks * 32;   // 16 halves = 32 bytes
            uint32_t af[2][4], bf[4][2];
            ldmatrix_x4(af[0][0], af[0][1], af[0][2], af[0][3], a_lm + kb);
            ldmatrix_x4(af[1][0], af[1][1], af[1][2], af[1][3],
                        a_lm + kb + 16 * LDA * 2);
            ldmatrix_x4(bf[0][0], bf[0][1], bf[1][0], bf[1][1], b_lm + kb);
            ldmatrix_x4(bf[2][0], bf[2][1], bf[3][0], bf[3][1],
                        b_lm + kb + 16 * LDB * 2);
#pragma unroll
            for (int mi = 0; mi < 2; mi++)
#pragma unroll
                for (int ni = 0; ni < 4; ni++)
                    mma16816(acc[mi][ni], af[mi][0], af[mi][1], af[mi][2], af[mi][3],
                             bf[ni][0], bf[ni][1]);
        }
        __syncthreads();   // Bs reads done; s_tile may overwrite

        // ---- bias + sigmoid -> s_tile ----
#pragma unroll
        for (int mi = 0; mi < 2; mi++) {
            int r = warp_m * 32 + mi * 16 + gi;
#pragma unroll
            for (int ni = 0; ni < 4; ni++) {
                int c = warp_n * 32 + ni * 8 + tig * 2;
                s_tile[r][c]         = sigmoidf(acc[mi][ni][0] + b_s[c]);
                s_tile[r][c + 1]     = sigmoidf(acc[mi][ni][1] + b_s[c + 1]);
                s_tile[r + 8][c]     = sigmoidf(acc[mi][ni][2] + b_s[c]);
                s_tile[r + 8][c + 1] = sigmoidf(acc[mi][ni][3] + b_s[c + 1]);
            }
        }
        __syncthreads();

        // ---- leaf probabilities (level-by-level, subtree q) + phi contraction ----
        {
            const float* sr = s_tile[r_leaf];
            float s0   = sr[0];
            float root = q ? s0 : 1.0f - s0;
            float sv   = sr[1 + q];
            float p2[2];
            p2[1] = root * sv; p2[0] = root - p2[1];
            float p4[4];
#pragma unroll
            for (int i = 0; i < 2; i++) {
                float s2 = sr[3 + 2 * q + i];
                p4[2 * i + 1] = p2[i] * s2; p4[2 * i] = p2[i] - p4[2 * i + 1];
            }
            float p8[8];
#pragma unroll
            for (int i = 0; i < 4; i++) {
                float s3 = sr[7 + 4 * q + i];
                p8[2 * i + 1] = p4[i] * s3; p8[2 * i] = p4[i] - p8[2 * i + 1];
            }
            float p16[16];
#pragma unroll
            for (int i = 0; i < 8; i++) {
                float s4 = sr[15 + 8 * q + i];
                p16[2 * i + 1] = p8[i] * s4; p16[2 * i] = p8[i] - p16[2 * i + 1];
            }
#pragma unroll
            for (int j = 0; j < 16; j++) {
                float s5  = sr[31 + 16 * q + j];
                float pr1 = p16[j] * s5;
                float pr0 = p16[j] - pr1;
                int l0 = q * 32 + 2 * j;
                float4 f0a = *reinterpret_cast<const float4*>(phi_s + l0 * P_);
                float4 f0b = *reinterpret_cast<const float4*>(phi_s + l0 * P_ + 4);
                float4 f1a = *reinterpret_cast<const float4*>(phi_s + (l0 + 1) * P_);
                float4 f1b = *reinterpret_cast<const float4*>(phi_s + (l0 + 1) * P_ + 4);
                partial[0] = fmaf(pr0, f0a.x, fmaf(pr1, f1a.x, partial[0]));
                partial[1] = fmaf(pr0, f0a.y, fmaf(pr1, f1a.y, partial[1]));
                partial[2] = fmaf(pr0, f0a.z, fmaf(pr1, f1a.z, partial[2]));
                partial[3] = fmaf(pr0, f0a.w, fmaf(pr1, f1a.w, partial[3]));
                partial[4] = fmaf(pr0, f0b.x, fmaf(pr1, f1b.x, partial[4]));
                partial[5] = fmaf(pr0, f0b.y, fmaf(pr1, f1b.y, partial[5]));
                partial[6] = fmaf(pr0, f0b.z, fmaf(pr1, f1b.z, partial[6]));
                partial[7] = fmaf(pr0, f0b.w, fmaf(pr1, f1b.w, partial[7]));
            }
        }
        __syncthreads();   // s_tile reads done; next tree may refill Bs
    }

    // pair-reduce the two subtree halves, then q==0 writes
#pragma unroll
    for (int p = 0; p < P_; p++)
        partial[p] += __shfl_xor_sync(0xffffffffu, partial[p], 1);

    if (q == 0) {
        float* o = g_partial + (size_t)tgrp * B_ * P_ + (size_t)(row0 + r_leaf) * P_;
        *reinterpret_cast<float4*>(o)     = make_float4(partial[0], partial[1], partial[2], partial[3]);
        *reinterpret_cast<float4*>(o + 4) = make_float4(partial[4], partial[5], partial[6], partial[7]);
    }
}

// ---------------- reduce over 8 tree-groups, apply shrinkage ----------------
__global__ void softgbm_reduce_kernel(float* __restrict__ out) {
    int i = blockIdx.x * blockDim.x + threadIdx.x;   // 0..B*P/4-1
    const float4* gp = reinterpret_cast<const float4*>(g_partial);
    float4 s = make_float4(0.f, 0.f, 0.f, 0.f);
#pragma unroll
    for (int g = 0; g < NGRP; g++) {
        float4 v = gp[(size_t)g * (B_ * P_ / 4) + i];
        s.x += v.x; s.y += v.y; s.z += v.z; s.w += v.w;
    }
    s.x *= 0.1f; s.y *= 0.1f; s.z *= 0.1f; s.w *= 0.1f;
    reinterpret_cast<float4*>(out)[i] = s;
}

extern "C" void kernel_launch(void* const* d_in, const int* in_sizes, int n_in,
                              void* d_out, int out_size) {
    (void)in_sizes; (void)n_in; (void)out_size;
    const float* x    = (const float*)d_in[0];
    const float* W    = (const float*)d_in[1];
    const float* bias = (const float*)d_in[2];
    const float* phi  = (const float*)d_in[3];
    float* out = (float*)d_out;

    cudaFuncSetAttribute(softgbm_main_kernel,
                         cudaFuncAttributeMaxDynamicSharedMemorySize, SMEM_DYN);

    dim3 grid(B_ / BM, NGRP);   // (64, 8) = 512 CTAs
    softgbm_main_kernel<<<grid, NTHREADS, SMEM_DYN>>>(x, W, bias, phi);

    softgbm_reduce_kernel<<<(B_ * P_ / 4) / 256, 256>>>(out);
}

// round 10
// speedup vs baseline: 3.1187x; 1.0021x over previous
#include <cuda_runtime.h>
#include <cuda_fp16.h>
#include <cstdint>

// Problem constants: B=8192, F=256, T=32, D=6 -> N=63, L=64, P=8
constexpr int B_     = 8192;
constexpr int F_     = 256;
constexpr int T_     = 32;
constexpr int NNODES = 63;
constexpr int LEAVES = 64;
constexpr int P_     = 8;

constexpr int BM = 128;
constexpr int BN = 64;
constexpr int NTHREADS = 256;        // 8 warps: 4(m) x 2(n), warp tile 32x32
constexpr int TREES_PER_BLK = 4;
constexpr int NGRP = T_ / TREES_PER_BLK;   // 8
constexpr int NTILES = B_ / BM;            // 64

constexpr int LDA = F_ + 8;          // 264 halfs/row -> 528B stride, 16B aligned
constexpr int LDB = F_ + 8;
constexpr int SMEM_A_BYTES = BM * LDA * 2;                 // 67584
constexpr int SMEM_B_BYTES = BN * LDB * 2;                 // 33792 (>= s_tile 33280)
constexpr int SMEM_DYN     = SMEM_A_BYTES + SMEM_B_BYTES;  // 101376 -> 2 CTAs/SM

// Per tree-group partials (deterministic reduction): 8 * 8192 * 8 floats = 2 MB.
__device__ __align__(16) float g_partial[(size_t)NGRP * B_ * P_];
__device__ int g_cnt[NTILES];   // zero-initialized; reset after use (graph replays)

__device__ __forceinline__ uint32_t smem_u32(const void* p) {
    uint32_t a;
    asm("{ .reg .u64 t; cvta.to.shared.u64 t, %1; cvt.u32.u64 %0, t; }"
        : "=r"(a) : "l"(p));
    return a;
}
__device__ __forceinline__ void ldmatrix_x4(uint32_t& r0, uint32_t& r1,
                                            uint32_t& r2, uint32_t& r3, uint32_t addr) {
    asm volatile("ldmatrix.sync.aligned.m8n8.x4.shared.b16 {%0,%1,%2,%3}, [%4];"
                 : "=r"(r0), "=r"(r1), "=r"(r2), "=r"(r3) : "r"(addr));
}
__device__ __forceinline__ void mma16816(float* c, uint32_t a0, uint32_t a1,
                                         uint32_t a2, uint32_t a3,
                                         uint32_t b0, uint32_t b1) {
    asm volatile(
        "mma.sync.aligned.m16n8k16.row.col.f32.f16.f16.f32 "
        "{%0,%1,%2,%3}, {%4,%5,%6,%7}, {%8,%9}, {%0,%1,%2,%3};"
        : "+f"(c[0]), "+f"(c[1]), "+f"(c[2]), "+f"(c[3])
        : "r"(a0), "r"(a1), "r"(a2), "r"(a3), "r"(b0), "r"(b1));
}
__device__ __forceinline__ float sigmoidf(float v) {
    return __fdividef(1.0f, 1.0f + __expf(-v));
}
__device__ __forceinline__ void prefetch_l2(const void* p) {
    asm volatile("prefetch.global.L2 [%0];" :: "l"(p));
}

__global__ __launch_bounds__(NTHREADS, 2)
void softgbm_main_kernel(const float* __restrict__ x,
                         const float* __restrict__ W,
                         const float* __restrict__ bias,
                         const float* __restrict__ phi,
                         float* __restrict__ out) {
    extern __shared__ __align__(16) char dsm[];
    __shared__ float phi_s[LEAVES * P_];
    __shared__ float b_s[BN];
    __shared__ int s_last;

    __half* As = reinterpret_cast<__half*>(dsm);                 // [128][LDA]
    __half* Bs = reinterpret_cast<__half*>(dsm + SMEM_A_BYTES);  // [64][LDB]
    float (*s_tile)[LEAVES + 1] =
        reinterpret_cast<float (*)[LEAVES + 1]>(dsm + SMEM_A_BYTES);  // aliases Bs

    const int tid  = threadIdx.x;
    const int wid  = tid >> 5;
    const int lane = tid & 31;
    const int tgrp = blockIdx.y;
    const int bx   = blockIdx.x;
    const int row0 = bx * BM;

    const int warp_m = wid >> 1;
    const int warp_n = wid & 1;
    const int gi  = lane >> 2;
    const int tig = lane & 3;

    // ---- fill As once: inline fp32 -> fp16 conversion of this block's x rows ----
#pragma unroll
    for (int it = 0; it < 16; it++) {
        int f = it * NTHREADS + tid;
        int r = f >> 5;
        int c = f & 31;
        const float* src = x + (size_t)(row0 + r) * F_ + c * 8;
        float4 v0 = *reinterpret_cast<const float4*>(src);
        float4 v1 = *reinterpret_cast<const float4*>(src + 4);
        __half2 h[4];
        h[0] = __floats2half2_rn(v0.x, v0.y);
        h[1] = __floats2half2_rn(v0.z, v0.w);
        h[2] = __floats2half2_rn(v1.x, v1.y);
        h[3] = __floats2half2_rn(v1.z, v1.w);
        *reinterpret_cast<uint4*>(As + (size_t)r * LDA + c * 8) =
            *reinterpret_cast<uint4*>(h);
    }

    const uint32_t as_u32 = smem_u32(As);
    const uint32_t bs_u32 = smem_u32(Bs);
    const uint32_t a_lm = as_u32 +
        ((uint32_t)(warp_m * 32 + (lane & 15)) * LDA + (lane >> 4) * 8) * 2;
    const uint32_t b_lm = bs_u32 +
        ((uint32_t)(warp_n * 32 + ((lane >> 4) & 1) * 8 + (lane & 7)) * LDB +
         ((lane >> 3) & 1) * 8) * 2;

    const int r_leaf = tid >> 1;
    const int q      = tid & 1;

    float partial[P_];
#pragma unroll
    for (int p = 0; p < P_; p++) partial[p] = 0.0f;

    for (int it_t = 0; it_t < TREES_PER_BLK; it_t++) {
        const int t = tgrp * TREES_PER_BLK + it_t;

        // ---- fill Bs (inline convert W_t), phi, bias ----
        const float* wt = W + (size_t)t * NNODES * F_;
#pragma unroll
        for (int it = 0; it < 8; it++) {
            int f = it * NTHREADS + tid;
            int n = f >> 5;
            int c = f & 31;
            __half2 h[4];
            if (n < NNODES) {
                const float* src = wt + (size_t)n * F_ + c * 8;
                float4 v0 = *reinterpret_cast<const float4*>(src);
                float4 v1 = *reinterpret_cast<const float4*>(src + 4);
                h[0] = __floats2half2_rn(v0.x, v0.y);
                h[1] = __floats2half2_rn(v0.z, v0.w);
                h[2] = __floats2half2_rn(v1.x, v1.y);
                h[3] = __floats2half2_rn(v1.z, v1.w);
            } else {
                h[0] = h[1] = h[2] = h[3] = __half2half2(__float2half(0.0f));
            }
            *reinterpret_cast<uint4*>(Bs + (size_t)n * LDB + c * 8) =
                *reinterpret_cast<uint4*>(h);
        }
        phi_s[tid]       = phi[(size_t)t * LEAVES * P_ + tid];
        phi_s[tid + 256] = phi[(size_t)t * LEAVES * P_ + tid + 256];
        if (tid < BN)
            b_s[tid] = (tid < NNODES) ? bias[(size_t)t * NNODES + tid] : 0.0f;
        __syncthreads();

        // L2-prefetch next tree's W (no registers held; overlaps GEMM+epilogue)
        if (it_t + 1 < TREES_PER_BLK) {
            const float* wn = W + (size_t)(t + 1) * NNODES * F_;
#pragma unroll
            for (int pf = 0; pf < 8; pf++) {
                int line = pf * NTHREADS + tid;        // 0..2047 (need 2016)
                if (line < NNODES * F_ * 4 / 128)
                    prefetch_l2(reinterpret_cast<const char*>(wn) + (size_t)line * 128);
            }
        }

        // ---- GEMM: 16 k-steps, ldmatrix fragments ----
        float acc[2][4][4];
#pragma unroll
        for (int mi = 0; mi < 2; mi++)
#pragma unroll
            for (int ni = 0; ni < 4; ni++)
#pragma unroll
                for (int j = 0; j < 4; j++) acc[mi][ni][j] = 0.0f;

#pragma unroll
        for (int ks = 0; ks < 16; ks++) {
            const uint32_t kb = (uint32_t)ks * 32;
            uint32_t af[2][4], bf[4][2];
            ldmatrix_x4(af[0][0], af[0][1], af[0][2], af[0][3], a_lm + kb);
            ldmatrix_x4(af[1][0], af[1][1], af[1][2], af[1][3],
                        a_lm + kb + 16 * LDA * 2);
            ldmatrix_x4(bf[0][0], bf[0][1], bf[1][0], bf[1][1], b_lm + kb);
            ldmatrix_x4(bf[2][0], bf[2][1], bf[3][0], bf[3][1],
                        b_lm + kb + 16 * LDB * 2);
#pragma unroll
            for (int mi = 0; mi < 2; mi++)
#pragma unroll
                for (int ni = 0; ni < 4; ni++)
                    mma16816(acc[mi][ni], af[mi][0], af[mi][1], af[mi][2], af[mi][3],
                             bf[ni][0], bf[ni][1]);
        }
        __syncthreads();   // Bs reads done; s_tile may overwrite

        // ---- bias + sigmoid -> s_tile ----
#pragma unroll
        for (int mi = 0; mi < 2; mi++) {
            int r = warp_m * 32 + mi * 16 + gi;
#pragma unroll
            for (int ni = 0; ni < 4; ni++) {
                int c = warp_n * 32 + ni * 8 + tig * 2;
                s_tile[r][c]         = sigmoidf(acc[mi][ni][0] + b_s[c]);
                s_tile[r][c + 1]     = sigmoidf(acc[mi][ni][1] + b_s[c + 1]);
                s_tile[r + 8][c]     = sigmoidf(acc[mi][ni][2] + b_s[c]);
                s_tile[r + 8][c + 1] = sigmoidf(acc[mi][ni][3] + b_s[c + 1]);
            }
        }
        __syncthreads();

        // ---- leaf probabilities (level-by-level, subtree q) + phi contraction ----
        {
            const float* sr = s_tile[r_leaf];
            float s0   = sr[0];
            float root = q ? s0 : 1.0f - s0;
            float sv   = sr[1 + q];
            float p2[2];
            p2[1] = root * sv; p2[0] = root - p2[1];
            float p4[4];
#pragma unroll
            for (int i = 0; i < 2; i++) {
                float s2 = sr[3 + 2 * q + i];
                p4[2 * i + 1] = p2[i] * s2; p4[2 * i] = p2[i] - p4[2 * i + 1];
            }
            float p8[8];
#pragma unroll
            for (int i = 0; i < 4; i++) {
                float s3 = sr[7 + 4 * q + i];
                p8[2 * i + 1] = p4[i] * s3; p8[2 * i] = p4[i] - p8[2 * i + 1];
            }
            float p16[16];
#pragma unroll
            for (int i = 0; i < 8; i++) {
                float s4 = sr[15 + 8 * q + i];
                p16[2 * i + 1] = p8[i] * s4; p16[2 * i] = p8[i] - p16[2 * i + 1];
            }
#pragma unroll
            for (int j = 0; j < 16; j++) {
                float s5  = sr[31 + 16 * q + j];
                float pr1 = p16[j] * s5;
                float pr0 = p16[j] - pr1;
                int l0 = q * 32 + 2 * j;
                float4 f0a = *reinterpret_cast<const float4*>(phi_s + l0 * P_);
                float4 f0b = *reinterpret_cast<const float4*>(phi_s + l0 * P_ + 4);
                float4 f1a = *reinterpret_cast<const float4*>(phi_s + (l0 + 1) * P_);
                float4 f1b = *reinterpret_cast<const float4*>(phi_s + (l0 + 1) * P_ + 4);
                partial[0] = fmaf(pr0, f0a.x, fmaf(pr1, f1a.x, partial[0]));
                partial[1] = fmaf(pr0, f0a.y, fmaf(pr1, f1a.y, partial[1]));
                partial[2] = fmaf(pr0, f0a.z, fmaf(pr1, f1a.z, partial[2]));
                partial[3] = fmaf(pr0, f0a.w, fmaf(pr1, f1a.w, partial[3]));
                partial[4] = fmaf(pr0, f0b.x, fmaf(pr1, f1b.x, partial[4]));
                partial[5] = fmaf(pr0, f0b.y, fmaf(pr1, f1b.y, partial[5]));
                partial[6] = fmaf(pr0, f0b.z, fmaf(pr1, f1b.z, partial[6]));
                partial[7] = fmaf(pr0, f0b.w, fmaf(pr1, f1b.w, partial[7]));
            }
        }
        __syncthreads();   // s_tile reads done; next tree may refill Bs
    }

    // pair-reduce the two subtree halves, then q==0 writes this group's partial
#pragma unroll
    for (int p = 0; p < P_; p++)
        partial[p] += __shfl_xor_sync(0xffffffffu, partial[p], 1);

    if (q == 0) {
        float* o = g_partial + (size_t)tgrp * B_ * P_ + (size_t)(row0 + r_leaf) * P_;
        *reinterpret_cast<float4*>(o)     = make_float4(partial[0], partial[1], partial[2], partial[3]);
        *reinterpret_cast<float4*>(o + 4) = make_float4(partial[4], partial[5], partial[6], partial[7]);
    }

    // ---- fused tail reduction: last CTA of this batch-tile sums all 8 groups ----
    __threadfence();
    __syncthreads();
    if (tid == 0) {
        int old = atomicAdd(&g_cnt[bx], 1);
        s_last = (old == NGRP - 1) ? 1 : 0;
        if (s_last) g_cnt[bx] = 0;     // reset for next graph replay
    }
    __syncthreads();
    if (s_last) {
        // 1024 outputs for this tile = 256 float4s; one per thread, fixed order sum.
        const size_t base = (size_t)row0 * P_ / 4;   // in float4 units
        float4 s = make_float4(0.f, 0.f, 0.f, 0.f);
#pragma unroll
        for (int g = 0; g < NGRP; g++) {
            const float4* gp = reinterpret_cast<const float4*>(
                g_partial + (size_t)g * B_ * P_);
            float4 v = gp[base + tid];
            s.x += v.x; s.y += v.y; s.z += v.z; s.w += v.w;
        }
        s.x *= 0.1f; s.y *= 0.1f; s.z *= 0.1f; s.w *= 0.1f;
        reinterpret_cast<float4*>(out)[base + tid] = s;
    }
}

extern "C" void kernel_launch(void* const* d_in, const int* in_sizes, int n_in,
                              void* d_out, int out_size) {
    (void)in_sizes; (void)n_in; (void)out_size;
    const float* x    = (const float*)d_in[0];
    const float* W    = (const float*)d_in[1];
    const float* bias = (const float*)d_in[2];
    const float* phi  = (const float*)d_in[3];
    float* out = (float*)d_out;

    cudaFuncSetAttribute(softgbm_main_kernel,
                         cudaFuncAttributeMaxDynamicSharedMemorySize, SMEM_DYN);

    dim3 grid(NTILES, NGRP);   // (64, 8) = 512 CTAs
    softgbm_main_kernel<<<grid, NTHREADS, SMEM_DYN>>>(x, W, bias, phi, out);
}

// round 13
// speedup vs baseline: 3.2060x; 1.0280x over previous
#include <cuda_runtime.h>
#include <cuda_fp16.h>
#include <cstdint>

// Problem constants: B=8192, F=256, T=32, D=6 -> N=63, L=64, P=8
constexpr int B_     = 8192;
constexpr int F_     = 256;
constexpr int T_     = 32;
constexpr int NNODES = 63;
constexpr int LEAVES = 64;
constexpr int P_     = 8;

constexpr int BM = 128;
constexpr int BN = 64;
constexpr int NTHREADS = 256;        // 8 warps: 4(m) x 2(n), warp tile 32x32
constexpr int TREES_PER_BLK = 4;
constexpr int NGRP = T_ / TREES_PER_BLK;   // 8
constexpr int NTILES = B_ / BM;            // 64

constexpr int LDA = F_ + 8;          // 264 halfs/row
constexpr int LDB = F_ + 8;
constexpr int SMEM_A_BYTES = BM * LDA * 2;                 // 67584
constexpr int SMEM_B_BYTES = BN * LDB * 2;                 // 33792 (>= s_tile 32768)
constexpr int SMEM_DYN     = SMEM_A_BYTES + SMEM_B_BYTES;  // 101376 -> 2 CTAs/SM

// Per tree-group partials (deterministic reduction): 8 * 8192 * 8 floats = 2 MB.
__device__ __align__(16) float g_partial[(size_t)NGRP * B_ * P_];
__device__ int g_cnt[NTILES];   // zero-initialized; reset by last CTA (graph replays)

__device__ __forceinline__ uint32_t smem_u32(const void* p) {
    uint32_t a;
    asm("{ .reg .u64 t; cvta.to.shared.u64 t, %1; cvt.u32.u64 %0, t; }"
        : "=r"(a) : "l"(p));
    return a;
}
__device__ __forceinline__ void ldmatrix_x4(uint32_t& r0, uint32_t& r1,
                                            uint32_t& r2, uint32_t& r3, uint32_t addr) {
    asm volatile("ldmatrix.sync.aligned.m8n8.x4.shared.b16 {%0,%1,%2,%3}, [%4];"
                 : "=r"(r0), "=r"(r1), "=r"(r2), "=r"(r3) : "r"(addr));
}
__device__ __forceinline__ void mma16816(float* c, uint32_t a0, uint32_t a1,
                                         uint32_t a2, uint32_t a3,
                                         uint32_t b0, uint32_t b1) {
    asm volatile(
        "mma.sync.aligned.m16n8k16.row.col.f32.f16.f16.f32 "
        "{%0,%1,%2,%3}, {%4,%5,%6,%7}, {%8,%9}, {%0,%1,%2,%3};"
        : "+f"(c[0]), "+f"(c[1]), "+f"(c[2]), "+f"(c[3])
        : "r"(a0), "r"(a1), "r"(a2), "r"(a3), "r"(b0), "r"(b1));
}
__device__ __forceinline__ float sigmoidf(float v) {
    return __fdividef(1.0f, 1.0f + __expf(-v));
}
__device__ __forceinline__ void prefetch_l2(const void* p) {
    asm volatile("prefetch.global.L2 [%0];" :: "l"(p));
}

__global__ __launch_bounds__(NTHREADS, 2)
void softgbm_main_kernel(const float* __restrict__ x,
                         const float* __restrict__ W,
                         const float* __restrict__ bias,
                         const float* __restrict__ phi,
                         float* __restrict__ out) {
    extern __shared__ __align__(16) char dsm[];
    __shared__ float phi_s[LEAVES * P_];
    __shared__ float b_s[BN];
    __shared__ int s_last;

    __half* As = reinterpret_cast<__half*>(dsm);                 // [128][LDA]
    __half* Bs = reinterpret_cast<__half*>(dsm + SMEM_A_BYTES);  // [64][LDB]
    // s_tile: fp32 [128 rows][64 cols], row stride 256B, 32B-granule XOR swizzle.
    // Aliases the Bs region (32768 <= 33792). LP buffers live inside s_tile.
    char* s_base = dsm + SMEM_A_BYTES;

    const int tid  = threadIdx.x;
    const int wid  = tid >> 5;
    const int lane = tid & 31;
    const int tgrp = blockIdx.y;
    const int bx   = blockIdx.x;
    const int row0 = bx * BM;

    const int warp_m = wid >> 1;
    const int warp_n = wid & 1;
    const int gi  = lane >> 2;     // 0..7
    const int tig = lane & 3;      // 0..3

    // ---- fill As once: inline fp32 -> fp16 conversion of this block's x rows ----
#pragma unroll
    for (int it = 0; it < 16; it++) {
        int f = it * NTHREADS + tid;
        int r = f >> 5;
        int c = f & 31;
        const float* src = x + (size_t)(row0 + r) * F_ + c * 8;
        float4 v0 = *reinterpret_cast<const float4*>(src);
        float4 v1 = *reinterpret_cast<const float4*>(src + 4);
        __half2 h[4];
        h[0] = __floats2half2_rn(v0.x, v0.y);
        h[1] = __floats2half2_rn(v0.z, v0.w);
        h[2] = __floats2half2_rn(v1.x, v1.y);
        h[3] = __floats2half2_rn(v1.z, v1.w);
        *reinterpret_cast<uint4*>(As + (size_t)r * LDA + c * 8) =
            *reinterpret_cast<uint4*>(h);
    }

    const uint32_t as_u32 = smem_u32(As);
    const uint32_t bs_u32 = smem_u32(Bs);
    const uint32_t a_lm = as_u32 +
        ((uint32_t)(warp_m * 32 + (lane & 15)) * LDA + (lane >> 4) * 8) * 2;
    const uint32_t b_lm = bs_u32 +
        ((uint32_t)(warp_n * 32 + ((lane >> 4) & 1) * 8 + (lane & 7)) * LDB +
         ((lane >> 3) & 1) * 8) * 2;

    // leafprob mapping: thread handles row r_leaf (= warp wid rows 16w..16w+15)
    const int r_leaf = tid >> 1;
    const int q      = tid & 1;
    const int rl7    = r_leaf & 7;

    // per-warp LP buffer: 16 rows x 64 halves (128B/row, 16B-granule XOR swizzle),
    // placed at this warp's OWN s_tile rows (bytes wid*4096 .. +2047) -> no extra smem.
    char* lp_base = s_base + wid * 4096;

    // contraction accumulator, persists across the 4 trees
    float accP[4] = {0.f, 0.f, 0.f, 0.f};

    for (int it_t = 0; it_t < TREES_PER_BLK; it_t++) {
        const int t = tgrp * TREES_PER_BLK + it_t;

        // ---- fill Bs (inline convert W_t), phi, bias ----
        const float* wt = W + (size_t)t * NNODES * F_;
#pragma unroll
        for (int it = 0; it < 8; it++) {
            int f = it * NTHREADS + tid;
            int n = f >> 5;
            int c = f & 31;
            __half2 h[4];
            if (n < NNODES) {
                const float* src = wt + (size_t)n * F_ + c * 8;
                float4 v0 = *reinterpret_cast<const float4*>(src);
                float4 v1 = *reinterpret_cast<const float4*>(src + 4);
                h[0] = __floats2half2_rn(v0.x, v0.y);
                h[1] = __floats2half2_rn(v0.z, v0.w);
                h[2] = __floats2half2_rn(v1.x, v1.y);
                h[3] = __floats2half2_rn(v1.z, v1.w);
            } else {
                h[0] = h[1] = h[2] = h[3] = __half2half2(__float2half(0.0f));
            }
            *reinterpret_cast<uint4*>(Bs + (size_t)n * LDB + c * 8) =
                *reinterpret_cast<uint4*>(h);
        }
        phi_s[tid]       = phi[(size_t)t * LEAVES * P_ + tid];
        phi_s[tid + 256] = phi[(size_t)t * LEAVES * P_ + tid + 256];
        if (tid < BN)
            b_s[tid] = (tid < NNODES) ? bias[(size_t)t * NNODES + tid] : 0.0f;
        __syncthreads();

        // L2-prefetch next tree's W
        if (it_t + 1 < TREES_PER_BLK) {
            const float* wn = W + (size_t)(t + 1) * NNODES * F_;
#pragma unroll
            for (int pf = 0; pf < 8; pf++) {
                int line = pf * NTHREADS + tid;
                if (line < NNODES * F_ * 4 / 128)
                    prefetch_l2(reinterpret_cast<const char*>(wn) + (size_t)line * 128);
            }
        }

        // ---- GEMM: 16 k-steps, ldmatrix fragments ----
        float acc[2][4][4];
#pragma unroll
        for (int mi = 0; mi < 2; mi++)
#pragma unroll
            for (int ni = 0; ni < 4; ni++)
#pragma unroll
                for (int j = 0; j < 4; j++) acc[mi][ni][j] = 0.0f;

#pragma unroll
        for (int ks = 0; ks < 16; ks++) {
            const uint32_t kb = (uint32_t)ks * 32;
            uint32_t af[2][4], bf[4][2];
            ldmatrix_x4(af[0][0], af[0][1], af[0][2], af[0][3], a_lm + kb);
            ldmatrix_x4(af[1][0], af[1][1], af[1][2], af[1][3],
                        a_lm + kb + 16 * LDA * 2);
            ldmatrix_x4(bf[0][0], bf[0][1], bf[1][0], bf[1][1], b_lm + kb);
            ldmatrix_x4(bf[2][0], bf[2][1], bf[3][0], bf[3][1],
                        b_lm + kb + 16 * LDB * 2);
#pragma unroll
            for (int mi = 0; mi < 2; mi++)
#pragma unroll
                for (int ni = 0; ni < 4; ni++)
                    mma16816(acc[mi][ni], af[mi][0], af[mi][1], af[mi][2], af[mi][3],
                             bf[ni][0], bf[ni][1]);
        }
        __syncthreads();   // Bs reads done; s_tile may overwrite

        // ---- bias + sigmoid -> swizzled fp32 s_tile (STS.64 pairs) ----
#pragma unroll
        for (int mi = 0; mi < 2; mi++) {
            int r = warp_m * 32 + mi * 16 + gi;   // r&7 == gi for both r and r+8
            const uint32_t swz = (uint32_t)gi << 5;
#pragma unroll
            for (int ni = 0; ni < 4; ni++) {
                int c = warp_n * 32 + ni * 8 + tig * 2;
                uint32_t cb = (uint32_t)c * 4;
                float2 lo = make_float2(sigmoidf(acc[mi][ni][0] + b_s[c]),
                                        sigmoidf(acc[mi][ni][1] + b_s[c + 1]));
                float2 hi = make_float2(sigmoidf(acc[mi][ni][2] + b_s[c]),
                                        sigmoidf(acc[mi][ni][3] + b_s[c + 1]));
                *reinterpret_cast<float2*>(s_base + (size_t)r * 256 + (cb ^ swz)) = lo;
                *reinterpret_cast<float2*>(s_base + (size_t)(r + 8) * 256 + (cb ^ swz)) = hi;
            }
        }
        __syncthreads();

        // ---- build phi B-fragments (B[n=p][k=l] = phi[l][p]) from phi_s ----
        uint32_t bphi[4][2];
#pragma unroll
        for (int ks = 0; ks < 4; ks++) {
            int k0 = 16 * ks + 2 * tig;
            __half2 h0 = __floats2half2_rn(phi_s[k0 * P_ + gi],
                                           phi_s[(k0 + 1) * P_ + gi]);
            __half2 h1 = __floats2half2_rn(phi_s[(k0 + 8) * P_ + gi],
                                           phi_s[(k0 + 9) * P_ + gi]);
            bphi[ks][0] = *reinterpret_cast<uint32_t*>(&h0);
            bphi[ks][1] = *reinterpret_cast<uint32_t*>(&h1);
        }

        // ---- leaf probabilities (level-by-level, subtree q) -> fp16 LP ----
        __half2 lp[16];
        {
            const char* srow = s_base + (size_t)r_leaf * 256;
            const uint32_t swz = (uint32_t)rl7 << 5;
            auto lds = [&](int n) -> float {
                return *reinterpret_cast<const float*>(srow + (((uint32_t)n * 4) ^ swz));
            };
            float s0   = lds(0);
            float root = q ? s0 : 1.0f - s0;
            float sv   = lds(1 + q);
            float p2[2];
            p2[1] = root * sv; p2[0] = root - p2[1];
            float p4[4];
#pragma unroll
            for (int i = 0; i < 2; i++) {
                float s2 = lds(3 + 2 * q + i);
                p4[2 * i + 1] = p2[i] * s2; p4[2 * i] = p2[i] - p4[2 * i + 1];
            }
            float p8[8];
#pragma unroll
            for (int i = 0; i < 4; i++) {
                float s3 = lds(7 + 4 * q + i);
                p8[2 * i + 1] = p4[i] * s3; p8[2 * i] = p4[i] - p8[2 * i + 1];
            }
            float p16[16];
#pragma unroll
            for (int i = 0; i < 8; i++) {
                float s4 = lds(15 + 8 * q + i);
                p16[2 * i + 1] = p8[i] * s4; p16[2 * i] = p8[i] - p16[2 * i + 1];
            }
#pragma unroll
            for (int j = 0; j < 16; j++) {
                float s5  = lds(31 + 16 * q + j);
                float pr1 = p16[j] * s5;
                float pr0 = p16[j] - pr1;
                lp[j] = __floats2half2_rn(pr0, pr1);
            }
        }
        __syncwarp();   // all s reads of this warp's rows done before LP overwrites them

        // store LP: local row i = r_leaf & 15, khalf = q*32 + 2j (swizzled 16B granule)
        {
            char* lw = lp_base + (size_t)(r_leaf & 15) * 128;
            const uint32_t swz = (uint32_t)rl7 << 4;
#pragma unroll
            for (int j = 0; j < 16; j++) {
                uint32_t kb = (uint32_t)(q * 64 + 4 * j);
                *reinterpret_cast<__half2*>(lw + (kb ^ swz)) = lp[j];
            }
        }
        __syncwarp();

        // ---- contraction MMA: LP[16x64] x phiT -> accP (accumulates over trees) ----
        {
            const uint32_t swzA = (uint32_t)gi << 4;   // gi = row&7 for both gi, gi+8
#pragma unroll
            for (int ks = 0; ks < 4; ks++) {
                uint32_t kb = (uint32_t)(32 * ks + 4 * tig);
                uint32_t a0 = *reinterpret_cast<const uint32_t*>(
                    lp_base + (size_t)gi * 128 + (kb ^ swzA));
                uint32_t a1 = *reinterpret_cast<const uint32_t*>(
                    lp_base + (size_t)(gi + 8) * 128 + (kb ^ swzA));
                uint32_t a2 = *reinterpret_cast<const uint32_t*>(
                    lp_base + (size_t)gi * 128 + ((kb + 16) ^ swzA));
                uint32_t a3 = *reinterpret_cast<const uint32_t*>(
                    lp_base + (size_t)(gi + 8) * 128 + ((kb + 16) ^ swzA));
                mma16816(accP, a0, a1, a2, a3, bphi[ks][0], bphi[ks][1]);
            }
        }
        __syncthreads();   // LP/s_tile region reads done; next tree may refill Bs
    }

    // ---- write this group's partial in MMA layout ----
    {
        int rg = row0 + 16 * wid + gi;
        float* o0 = g_partial + (size_t)tgrp * B_ * P_ + (size_t)rg * P_ + 2 * tig;
        float* o1 = o0 + 8 * P_;
        *reinterpret_cast<float2*>(o0) = make_float2(accP[0], accP[1]);
        *reinterpret_cast<float2*>(o1) = make_float2(accP[2], accP[3]);
    }

    // ---- fused tail reduction: last CTA of this batch-tile sums all 8 groups ----
    __threadfence();
    __syncthreads();
    if (tid == 0) {
        int old = atomicAdd(&g_cnt[bx], 1);
        s_last = (old == NGRP - 1) ? 1 : 0;
        if (s_last) g_cnt[bx] = 0;     // reset for next graph replay
    }
    __syncthreads();
    if (s_last) {
        __threadfence();               // acquire side of the counter handshake
        const size_t base = (size_t)row0 * P_ / 4;   // in float4 units
        float4 s = make_float4(0.f, 0.f, 0.f, 0.f);
#pragma unroll
        for (int g = 0; g < NGRP; g++) {
            const float4* gp = reinterpret_cast<const float4*>(
                g_partial + (size_t)g * B_ * P_);
            float4 v = gp[base + tid];
            s.x += v.x; s.y += v.y; s.z += v.z; s.w += v.w;
        }
        s.x *= 0.1f; s.y *= 0.1f; s.z *= 0.1f; s.w *= 0.1f;
        reinterpret_cast<float4*>(out)[base + tid] = s;
    }
}

extern "C" void kernel_launch(void* const* d_in, const int* in_sizes, int n_in,
                              void* d_out, int out_size) {
    (void)in_sizes; (void)n_in; (void)out_size;
    const float* x    = (const float*)d_in[0];
    const float* W    = (const float*)d_in[1];
    const float* bias = (const float*)d_in[2];
    const float* phi  = (const float*)d_in[3];
    float* out = (float*)d_out;

    cudaFuncSetAttribute(softgbm_main_kernel,
                         cudaFuncAttributeMaxDynamicSharedMemorySize, SMEM_DYN);

    dim3 grid(NTILES, NGRP);   // (64, 8) = 512 CTAs
    softgbm_main_kernel<<<grid, NTHREADS, SMEM_DYN>>>(x, W, bias, phi, out);
}

// round 14
// speedup vs baseline: 4.1787x; 1.3034x over previous
#include <cuda_runtime.h>
#include <cuda_fp16.h>
#include <cstdint>

// Problem constants: B=8192, F=256, T=32, D=6 -> N=63, L=64, P=8
constexpr int B_     = 8192;
constexpr int F_     = 256;
constexpr int T_     = 32;
constexpr int NNODES = 63;
constexpr int LEAVES = 64;
constexpr int P_     = 8;

constexpr int BM = 128;
constexpr int BN = 64;
constexpr int NTHREADS = 256;        // 8 warps: 4(m) x 2(n), warp tile 32x32
constexpr int TREES_PER_BLK = 4;
constexpr int NGRP = T_ / TREES_PER_BLK;   // 8
constexpr int NTILES = B_ / BM;            // 64

constexpr int LDA = F_ + 8;          // 264 halfs/row
constexpr int LDB = F_ + 8;
constexpr int SMEM_A_BYTES = BM * LDA * 2;                 // 67584
constexpr int SMEM_B_BYTES = BN * LDB * 2;                 // 33792 (>= s_tile 32768)
constexpr int SMEM_DYN     = SMEM_A_BYTES + SMEM_B_BYTES;  // 101376 -> 2 CTAs/SM

// Scratch: per tree-group partials + fp16-converted inputs.
__device__ __align__(16) float  g_partial[(size_t)NGRP * B_ * P_];
__device__ int g_cnt[NTILES];   // zero-initialized; reset by last CTA (graph replays)
__device__ __align__(16) __half g_xh[(size_t)B_ * F_];
__device__ __align__(16) __half g_wh[(size_t)T_ * NNODES * F_];

__device__ __forceinline__ uint32_t smem_u32(const void* p) {
    uint32_t a;
    asm("{ .reg .u64 t; cvta.to.shared.u64 t, %1; cvt.u32.u64 %0, t; }"
        : "=r"(a) : "l"(p));
    return a;
}
__device__ __forceinline__ void ldmatrix_x4(uint32_t& r0, uint32_t& r1,
                                            uint32_t& r2, uint32_t& r3, uint32_t addr) {
    asm volatile("ldmatrix.sync.aligned.m8n8.x4.shared.b16 {%0,%1,%2,%3}, [%4];"
                 : "=r"(r0), "=r"(r1), "=r"(r2), "=r"(r3) : "r"(addr));
}
__device__ __forceinline__ void mma16816(float* c, uint32_t a0, uint32_t a1,
                                         uint32_t a2, uint32_t a3,
                                         uint32_t b0, uint32_t b1) {
    asm volatile(
        "mma.sync.aligned.m16n8k16.row.col.f32.f16.f16.f32 "
        "{%0,%1,%2,%3}, {%4,%5,%6,%7}, {%8,%9}, {%0,%1,%2,%3};"
        : "+f"(c[0]), "+f"(c[1]), "+f"(c[2]), "+f"(c[3])
        : "r"(a0), "r"(a1), "r"(a2), "r"(a3), "r"(b0), "r"(b1));
}
__device__ __forceinline__ float sigmoidf(float v) {
    return __fdividef(1.0f, 1.0f + __expf(-v));
}
__device__ __forceinline__ void prefetch_l2(const void* p) {
    asm volatile("prefetch.global.L2 [%0];" :: "l"(p));
}
// Bank bijection: 4 row bits -> bank bits {0,1,3,4} (disjoint from tig bits {1,2}
// for rows 0..7, constant-offset for rows 8..15).
__device__ __forceinline__ uint32_t vswz(uint32_t rl) {
    return ((rl & 3u) << 3) | ((rl >> 2) & 1u) | (((rl >> 3) & 1u) << 1);
}

// ---------------- prep: fp32 -> fp16 conversion of x and W ----------------
__global__ void softgbm_prep(const float* __restrict__ x, const float* __restrict__ W) {
    int i = blockIdx.x * blockDim.x + threadIdx.x;
    constexpr int NX4 = B_ * F_ / 4;
    constexpr int NW4 = T_ * NNODES * F_ / 4;
    if (i < NX4) {
        float4 v = reinterpret_cast<const float4*>(x)[i];
        __half2* o = reinterpret_cast<__half2*>(g_xh);
        o[2 * i]     = __floats2half2_rn(v.x, v.y);
        o[2 * i + 1] = __floats2half2_rn(v.z, v.w);
    } else if (i < NX4 + NW4) {
        int j = i - NX4;
        float4 v = reinterpret_cast<const float4*>(W)[j];
        __half2* o = reinterpret_cast<__half2*>(g_wh);
        o[2 * j]     = __floats2half2_rn(v.x, v.y);
        o[2 * j + 1] = __floats2half2_rn(v.z, v.w);
    }
}

__global__ __launch_bounds__(NTHREADS, 2)
void softgbm_main_kernel(const float* __restrict__ bias,
                         const float* __restrict__ phi,
                         float* __restrict__ out) {
    extern __shared__ __align__(16) char dsm[];
    __shared__ float phi_s[LEAVES * P_];
    __shared__ float b_s[BN];
    __shared__ int s_last;

    __half* As = reinterpret_cast<__half*>(dsm);                 // [128][LDA]
    __half* Bs = reinterpret_cast<__half*>(dsm + SMEM_A_BYTES);  // [64][LDB]
    // s_tile: fp32 [128 rows][64 cols], row stride 256B, v-swizzled columns.
    char* s_base = dsm + SMEM_A_BYTES;                           // aliases Bs

    const int tid  = threadIdx.x;
    const int wid  = tid >> 5;
    const int lane = tid & 31;
    const int tgrp = blockIdx.y;
    const int bx   = blockIdx.x;
    const int row0 = bx * BM;

    const int warp_m = wid >> 1;
    const int warp_n = wid & 1;
    const int gi  = lane >> 2;     // 0..7
    const int tig = lane & 3;      // 0..3

    // ---- fill As once from pre-converted fp16 x ----
    {
        const __half* xh = g_xh + (size_t)row0 * F_;
#pragma unroll
        for (int it = 0; it < 16; it++) {
            int f = it * NTHREADS + tid;   // 0..4095 16B chunks
            int r = f >> 5;
            int c = f & 31;
            uint4 v = *reinterpret_cast<const uint4*>(xh + (size_t)r * F_ + c * 8);
            *reinterpret_cast<uint4*>(As + (size_t)r * LDA + c * 8) = v;
        }
    }

    const uint32_t as_u32 = smem_u32(As);
    const uint32_t bs_u32 = smem_u32(Bs);
    const uint32_t a_lm = as_u32 +
        ((uint32_t)(warp_m * 32 + (lane & 15)) * LDA + (lane >> 4) * 8) * 2;
    const uint32_t b_lm = bs_u32 +
        ((uint32_t)(warp_n * 32 + ((lane >> 4) & 1) * 8 + (lane & 7)) * LDB +
         ((lane >> 3) & 1) * 8) * 2;

    // leafprob mapping: thread handles row r_leaf (warp wid owns rows 16w..16w+15)
    const int r_leaf = tid >> 1;
    const int q      = tid & 1;
    const uint32_t v_leaf = vswz((uint32_t)r_leaf & 15);
    const int rl7 = r_leaf & 7;

    // per-warp LP buffer: 16 rows x 64 halves (128B/row, 16B-granule XOR swizzle),
    // placed at this warp's OWN s_tile rows -> no extra smem.
    char* lp_base = s_base + wid * 4096;

    float accP[4] = {0.f, 0.f, 0.f, 0.f};

    for (int it_t = 0; it_t < TREES_PER_BLK; it_t++) {
        const int t = tgrp * TREES_PER_BLK + it_t;

        // ---- fill Bs from pre-converted fp16 W ----
        const __half* wh = g_wh + (size_t)t * NNODES * F_;
#pragma unroll
        for (int it = 0; it < 8; it++) {
            int f = it * NTHREADS + tid;   // 0..2047 16B chunks
            int n = f >> 5;
            int c = f & 31;
            uint4 v = make_uint4(0u, 0u, 0u, 0u);
            if (n < NNODES)
                v = *reinterpret_cast<const uint4*>(wh + (size_t)n * F_ + c * 8);
            *reinterpret_cast<uint4*>(Bs + (size_t)n * LDB + c * 8) = v;
        }
        phi_s[tid]       = phi[(size_t)t * LEAVES * P_ + tid];
        phi_s[tid + 256] = phi[(size_t)t * LEAVES * P_ + tid + 256];
        if (tid < BN)
            b_s[tid] = (tid < NNODES) ? bias[(size_t)t * NNODES + tid] : 0.0f;
        __syncthreads();

        // L2-prefetch next tree's W (fp16: 32KB = 256 lines)
        if (it_t + 1 < TREES_PER_BLK) {
            const char* wn = reinterpret_cast<const char*>(
                g_wh + (size_t)(t + 1) * NNODES * F_);
            if (tid < NNODES * F_ * 2 / 128)
                prefetch_l2(wn + (size_t)tid * 128);
        }

        // ---- GEMM: 16 k-steps, ldmatrix fragments ----
        float acc[2][4][4];
#pragma unroll
        for (int mi = 0; mi < 2; mi++)
#pragma unroll
            for (int ni = 0; ni < 4; ni++)
#pragma unroll
                for (int j = 0; j < 4; j++) acc[mi][ni][j] = 0.0f;

#pragma unroll
        for (int ks = 0; ks < 16; ks++) {
            const uint32_t kb = (uint32_t)ks * 32;
            uint32_t af[2][4], bf[4][2];
            ldmatrix_x4(af[0][0], af[0][1], af[0][2], af[0][3], a_lm + kb);
            ldmatrix_x4(af[1][0], af[1][1], af[1][2], af[1][3],
                        a_lm + kb + 16 * LDA * 2);
            ldmatrix_x4(bf[0][0], bf[0][1], bf[1][0], bf[1][1], b_lm + kb);
            ldmatrix_x4(bf[2][0], bf[2][1], bf[3][0], bf[3][1],
                        b_lm + kb + 16 * LDB * 2);
#pragma unroll
            for (int mi = 0; mi < 2; mi++)
#pragma unroll
                for (int ni = 0; ni < 4; ni++)
                    mma16816(acc[mi][ni], af[mi][0], af[mi][1], af[mi][2], af[mi][3],
                             bf[ni][0], bf[ni][1]);
        }
        __syncthreads();   // Bs reads done; s_tile may overwrite

        // ---- bias + sigmoid -> v-swizzled fp32 s_tile (conflict-free STS.32) ----
        {
            // rows r=...+gi have rl15==gi; rows r+8 have rl15==gi+8 (v differs by bit1,
            // constant across the instr's lanes -> distinctness preserved).
            const uint32_t v_lo = vswz((uint32_t)gi);
            const uint32_t v_hi = v_lo | 2u;
#pragma unroll
            for (int mi = 0; mi < 2; mi++) {
                int r = warp_m * 32 + mi * 16 + gi;
                char* row_lo = s_base + (size_t)r * 256;
                char* row_hi = s_base + (size_t)(r + 8) * 256;
#pragma unroll
                for (int ni = 0; ni < 4; ni++) {
                    uint32_t c0 = (uint32_t)(warp_n * 32 + ni * 8 + tig * 2);
                    *reinterpret_cast<float*>(row_lo + ((c0 ^ v_lo) << 2)) =
                        sigmoidf(acc[mi][ni][0] + b_s[c0]);
                    *reinterpret_cast<float*>(row_lo + (((c0 + 1) ^ v_lo) << 2)) =
                        sigmoidf(acc[mi][ni][1] + b_s[c0 + 1]);
                    *reinterpret_cast<float*>(row_hi + ((c0 ^ v_hi) << 2)) =
                        sigmoidf(acc[mi][ni][2] + b_s[c0]);
                    *reinterpret_cast<float*>(row_hi + (((c0 + 1) ^ v_hi) << 2)) =
                        sigmoidf(acc[mi][ni][3] + b_s[c0 + 1]);
                }
            }
        }
        __syncthreads();

        // ---- build phi B-fragments (B[n=p][k=l] = phi[l][p]) from phi_s ----
        uint32_t bphi[4][2];
#pragma unroll
        for (int ks = 0; ks < 4; ks++) {
            int k0 = 16 * ks + 2 * tig;
            __half2 h0 = __floats2half2_rn(phi_s[k0 * P_ + gi],
                                           phi_s[(k0 + 1) * P_ + gi]);
            __half2 h1 = __floats2half2_rn(phi_s[(k0 + 8) * P_ + gi],
                                           phi_s[(k0 + 9) * P_ + gi]);
            bphi[ks][0] = *reinterpret_cast<uint32_t*>(&h0);
            bphi[ks][1] = *reinterpret_cast<uint32_t*>(&h1);
        }

        // ---- leaf probabilities (level-by-level, subtree q) -> fp16 LP ----
        __half2 lp[16];
        {
            const char* srow = s_base + (size_t)r_leaf * 256;
            auto lds = [&](int n) -> float {
                return *reinterpret_cast<const float*>(
                    srow + ((((uint32_t)n) ^ v_leaf) << 2));
            };
            float s0   = lds(0);
            float root = q ? s0 : 1.0f - s0;
            float sv   = lds(1 + q);
            float p2[2];
            p2[1] = root * sv; p2[0] = root - p2[1];
            float p4[4];
#pragma unroll
            for (int i = 0; i < 2; i++) {
                float s2 = lds(3 + 2 * q + i);
                p4[2 * i + 1] = p2[i] * s2; p4[2 * i] = p2[i] - p4[2 * i + 1];
            }
            float p8[8];
#pragma unroll
            for (int i = 0; i < 4; i++) {
                float s3 = lds(7 + 4 * q + i);
                p8[2 * i + 1] = p4[i] * s3; p8[2 * i] = p4[i] - p8[2 * i + 1];
            }
            float p16[16];
#pragma unroll
            for (int i = 0; i < 8; i++) {
                float s4 = lds(15 + 8 * q + i);
                p16[2 * i + 1] = p8[i] * s4; p16[2 * i] = p8[i] - p16[2 * i + 1];
            }
#pragma unroll
            for (int j = 0; j < 16; j++) {
                float s5  = lds(31 + 16 * q + j);
                float pr1 = p16[j] * s5;
                float pr0 = p16[j] - pr1;
                lp[j] = __floats2half2_rn(pr0, pr1);
            }
        }
        __syncwarp();   // all s reads of this warp's rows done before LP overwrites

        // store LP: local row = r_leaf & 15, khalf = q*32 + 2j (16B-granule XOR)
        {
            char* lw = lp_base + (size_t)(r_leaf & 15) * 128;
            const uint32_t swz = (uint32_t)rl7 << 4;
#pragma unroll
            for (int j = 0; j < 16; j++) {
                uint32_t kb = (uint32_t)(q * 64 + 4 * j);
                *reinterpret_cast<__half2*>(lw + (kb ^ swz)) = lp[j];
            }
        }
        __syncwarp();

        // ---- contraction MMA: LP[16x64] x phiT -> accP (accumulates over trees) ----
        {
            const uint32_t swzA = (uint32_t)gi << 4;
#pragma unroll
            for (int ks = 0; ks < 4; ks++) {
                uint32_t kb = (uint32_t)(32 * ks + 4 * tig);
                uint32_t a0 = *reinterpret_cast<const uint32_t*>(
                    lp_base + (size_t)gi * 128 + (kb ^ swzA));
                uint32_t a1 = *reinterpret_cast<const uint32_t*>(
                    lp_base + (size_t)(gi + 8) * 128 + (kb ^ swzA));
                uint32_t a2 = *reinterpret_cast<const uint32_t*>(
                    lp_base + (size_t)gi * 128 + ((kb + 16) ^ swzA));
                uint32_t a3 = *reinterpret_cast<const uint32_t*>(
                    lp_base + (size_t)(gi + 8) * 128 + ((kb + 16) ^ swzA));
                mma16816(accP, a0, a1, a2, a3, bphi[ks][0], bphi[ks][1]);
            }
        }
        __syncthreads();   // region reads done; next tree may refill Bs
    }

    // ---- write this group's partial in MMA layout ----
    {
        int rg = row0 + 16 * wid + gi;
        float* o0 = g_partial + (size_t)tgrp * B_ * P_ + (size_t)rg * P_ + 2 * tig;
        float* o1 = o0 + 8 * P_;
        *reinterpret_cast<float2*>(o0) = make_float2(accP[0], accP[1]);
        *reinterpret_cast<float2*>(o1) = make_float2(accP[2], accP[3]);
    }

    // ---- fused tail reduction: last CTA of this batch-tile sums all 8 groups ----
    __threadfence();
    __syncthreads();
    if (tid == 0) {
        int old = atomicAdd(&g_cnt[bx], 1);
        s_last = (old == NGRP - 1) ? 1 : 0;
        if (s_last) g_cnt[bx] = 0;     // reset for next graph replay
    }
    __syncthreads();
    if (s_last) {
        __threadfence();               // acquire side of the counter handshake
        const size_t base = (size_t)row0 * P_ / 4;   // float4 units
        float4 s = make_float4(0.f, 0.f, 0.f, 0.f);
#pragma unroll
        for (int g = 0; g < NGRP; g++) {
            const float4* gp = reinterpret_cast<const float4*>(
                g_partial + (size_t)g * B_ * P_);
            float4 v = gp[base + tid];
            s.x += v.x; s.y += v.y; s.z += v.z; s.w += v.w;
        }
        s.x *= 0.1f; s.y *= 0.1f; s.z *= 0.1f; s.w *= 0.1f;
        reinterpret_cast<float4*>(out)[base + tid] = s;
    }
}

extern "C" void kernel_launch(void* const* d_in, const int* in_sizes, int n_in,
                              void* d_out, int out_size) {
    (void)in_sizes; (void)n_in; (void)out_size;
    const float* x    = (const float*)d_in[0];
    const float* W    = (const float*)d_in[1];
    const float* bias = (const float*)d_in[2];
    const float* phi  = (const float*)d_in[3];
    float* out = (float*)d_out;

    cudaFuncSetAttribute(softgbm_main_kernel,
                         cudaFuncAttributeMaxDynamicSharedMemorySize, SMEM_DYN);

    constexpr int NCVT = (B_ * F_ + T_ * NNODES * F_) / 4;
    softgbm_prep<<<(NCVT + 255) / 256, 256>>>(x, W);

    dim3 grid(NTILES, NGRP);   // (64, 8) = 512 CTAs
    softgbm_main_kernel<<<grid, NTHREADS, SMEM_DYN>>>(bias, phi, out);
}